// round 8
// baseline (speedup 1.0000x reference)
#include <cuda_runtime.h>
#include <cuda_bf16.h>
#include <cstdint>

#define NN    100000
#define RR    7
#define DD    64
#define EDIM  16
#define KU    448              // R*D
#define KTOT  512              // 448 (U) + 64 (x)
#define EMAX  1600000

typedef unsigned long long ull;

// Scratch
__device__ float g_U[(size_t)NN * KU];              // 179.2 MB (written once, no atomics)
__device__ float g_Wp[128 * 32 * 8];                // 128 KB interleaved combined weights
__device__ float g_bias[DD];
__device__ int   g_cnt[NN];                         // per-node edge counts
__device__ int   g_start[NN + 1];                   // CSR offsets (preserved)
__device__ int   g_ofs[NN];                         // working cursor for scatter
__device__ int   g_eord[EMAX];                      // edge indices sorted by dest node

// ---- f32x2 helpers (sm_103a packed FMA) -----------------------------------
__device__ __forceinline__ ull f2fma(ull a, ull b, ull c) {
    ull d; asm("fma.rn.f32x2 %0, %1, %2, %3;" : "=l"(d) : "l"(a), "l"(b), "l"(c)); return d;
}
__device__ __forceinline__ ull pk2(float w) {
    ull r; asm("mov.b64 %0, {%1, %1};" : "=l"(r) : "f"(w)); return r;
}
__device__ __forceinline__ float2 up2(ull v) {
    float2 r; asm("mov.b64 {%0, %1}, %2;" : "=f"(r.x), "=f"(r.y) : "l"(v)); return r;
}

// ---------------------------------------------------------------------------
// K0: build interleaved combined weight + bias
// ---------------------------------------------------------------------------
__global__ void prep_kernel(const float* __restrict__ W_lin,  const float* __restrict__ b_lin,
                            const float* __restrict__ W_self, const float* __restrict__ b_self) {
    int tid = blockIdx.x * blockDim.x + threadIdx.x;
    const int total = 128 * 32 * 8;
    for (int idx = tid; idx < total; idx += gridDim.x * blockDim.x) {
        int kk  = idx >> 8;
        int rem = idx & 255;
        int cg  = rem >> 3;
        int r8  = rem & 7;
        int s   = r8 >> 2;
        int j   = r8 & 3;
        int col = 2 * cg + s;
        int k   = 4 * kk + j;
        float v = (k < KU) ? W_lin[col * KU + k]
                           : W_self[col * DD + (k - KU)];
        g_Wp[idx] = v;
    }
    if (tid < DD) g_bias[tid] = b_lin[tid] + b_self[tid];
}

// ---------------------------------------------------------------------------
// Sort pipeline: zero counts -> histogram -> scan -> scatter edge indices
// ---------------------------------------------------------------------------
__global__ void zcnt_kernel() {
    int i = blockIdx.x * blockDim.x + threadIdx.x;
    if (i < NN) g_cnt[i] = 0;
}

__global__ void hist_kernel(const int* __restrict__ elist, int E) {
    int stride = gridDim.x * blockDim.x;
    for (int e = blockIdx.x * blockDim.x + threadIdx.x; e < E; e += stride) {
        int no = elist[3 * e + 1];
        atomicAdd(&g_cnt[no], 1);
    }
}

__global__ void scan_kernel(int E) {     // <<<1, 1024>>>
    __shared__ int sums[1024];
    const int PER = (NN + 1023) / 1024;  // 98
    int t  = threadIdx.x;
    int lo = t * PER;
    int hi = lo + PER; if (hi > NN) hi = NN;

    int s = 0;
    for (int i = lo; i < hi; i++) s += g_cnt[i];
    sums[t] = s;
    __syncthreads();
    // inclusive Hillis-Steele scan
    for (int off = 1; off < 1024; off <<= 1) {
        int v = (t >= off) ? sums[t - off] : 0;
        __syncthreads();
        sums[t] += v;
        __syncthreads();
    }
    int running = (t == 0) ? 0 : sums[t - 1];
    for (int i = lo; i < hi; i++) {
        int c = g_cnt[i];
        g_start[i] = running;
        g_ofs[i]   = running;
        running += c;
    }
    if (t == 1023) g_start[NN] = running;   // == E
}

__global__ void scatter_kernel(const int* __restrict__ elist, int E) {
    int stride = gridDim.x * blockDim.x;
    for (int e = blockIdx.x * blockDim.x + threadIdx.x; e < E; e += stride) {
        int no  = elist[3 * e + 1];
        int pos = atomicAdd(&g_ofs[no], 1);
        g_eord[pos] = e;
    }
}

// ---------------------------------------------------------------------------
// K2: sorted edge accumulation, NO atomics.
//     Block = 32 nodes, 512 threads. 16-lane group gi owns node base+gi and
//     processes all its edges sequentially into its exclusive smem U-row.
//     Then coalesced dump of all 32 rows (incl. untouched zeros) to g_U.
// ---------------------------------------------------------------------------
__global__ __launch_bounds__(512) void edge_sorted_kernel(
        const float* __restrict__ x,
        const int*   __restrict__ elist,
        const float* __restrict__ ew,
        const float* __restrict__ ef,
        const float* __restrict__ W_edge,
        const float* __restrict__ b_edge,
        int E, int Nn) {
    __shared__ float4 We_sh[EDIM * 16];   // We_sh[d*16+t] = W_edge rows 4t..4t+3, dim d
    __shared__ float4 be_sh[16];
    __shared__ float  U_sh[32 * KU];      // 56 KB, one 448-row per node

    int tid = threadIdx.x;
    if (tid < 256) {
        int d = tid / 16, t = tid % 16;
        float4 v;
        v.x = W_edge[(4 * t + 0) * EDIM + d];
        v.y = W_edge[(4 * t + 1) * EDIM + d];
        v.z = W_edge[(4 * t + 2) * EDIM + d];
        v.w = W_edge[(4 * t + 3) * EDIM + d];
        We_sh[tid] = v;
        if (tid < 16) be_sh[tid] = reinterpret_cast<const float4*>(b_edge)[tid];
    }
    // zero U_sh: 3584 float4s / 512 threads = 7 each
    float4* U4 = reinterpret_cast<float4*>(U_sh);
#pragma unroll
    for (int it = 0; it < 7; it++)
        U4[it * 512 + tid] = make_float4(0.f, 0.f, 0.f, 0.f);
    __syncthreads();

    int gi = tid >> 4;          // group 0..31 -> node
    int t  = tid & 15;          // lane within group -> dims 4t..4t+3
    int n  = blockIdx.x * 32 + gi;

    if (n < Nn) {
        int s0 = g_start[n];
        int s1 = g_start[n + 1];
        float* Urow = U_sh + gi * KU;

        int e = (s0 < s1) ? g_eord[s0] : 0;
        for (int s = s0; s < s1; s++) {
            int e_nxt = (s + 1 < s1) ? g_eord[s + 1] : 0;

            int   ni  = elist[3 * e + 0];
            int   rel = elist[3 * e + 2];
            float w   = ew[e];

            const float4* efv = reinterpret_cast<const float4*>(ef + (size_t)e * EDIM);
            float4 acc = be_sh[t];
#pragma unroll
            for (int g = 0; g < 4; g++) {
                float4 fg = efv[g];
                float vals[4] = {fg.x, fg.y, fg.z, fg.w};
#pragma unroll
                for (int q = 0; q < 4; q++) {
                    float4 wv = We_sh[(4 * g + q) * 16 + t];
                    float  fd = vals[q];
                    acc.x += wv.x * fd;
                    acc.y += wv.y * fd;
                    acc.z += wv.z * fd;
                    acc.w += wv.w * fd;
                }
            }
            float4 xg = reinterpret_cast<const float4*>(x + (size_t)ni * DD)[t];
            float4* dst = reinterpret_cast<float4*>(Urow + rel * DD + 4 * t);
            float4 cur = *dst;
            cur.x += w * (xg.x + acc.x);
            cur.y += w * (xg.y + acc.y);
            cur.z += w * (xg.z + acc.z);
            cur.w += w * (xg.w + acc.w);
            *dst = cur;

            e = e_nxt;
        }
    }
    __syncthreads();

    // dump all 32 rows to g_U, coalesced (rows of empty nodes stay zero)
    int base = blockIdx.x * 32;
#pragma unroll
    for (int it = 0; it < 7; it++) {
        int idx = it * 512 + tid;
        int nl  = idx / 112;          // 448/4 float4s per row
        int k4  = idx % 112;
        int n2  = base + nl;
        if (n2 < Nn)
            reinterpret_cast<float4*>(g_U + (size_t)n2 * KU)[k4] = U4[idx];
    }
}

// ---------------------------------------------------------------------------
// K3: register-blocked GEMM with packed f32x2 FMA, K-split staging (2 x 32KB).
//     out = relu([U‖x](N x 512) @ Wc(512 x 64) + bias)
//     __launch_bounds__(128, 6): cap regs so occupancy = 6 blocks/SM.
// ---------------------------------------------------------------------------
__global__ __launch_bounds__(128, 6) void out_kernel(const float* __restrict__ x,
                                                     float* __restrict__ out, int Nn) {
    __shared__ __align__(16) ull u2[16 * 256];   // 16 pairs x 256 k-slice
    int tid  = threadIdx.x;
    int base = blockIdx.x * 32;

    int cg = tid & 31;
    int g  = tid >> 5;

    float bc0 = g_bias[2 * cg];
    float bc1 = g_bias[2 * cg + 1];
    ull acc[4][2];
#pragma unroll
    for (int q = 0; q < 4; q++) { acc[q][0] = pk2(bc0); acc[q][1] = pk2(bc1); }

#pragma unroll
    for (int h = 0; h < 2; h++) {
        if (h) __syncthreads();

        // stage k in [h*256, h*256+256), pre-packed float2, coalesced
#pragma unroll
        for (int it = 0; it < 32; it++) {
            int idx = it * 128 + tid;
            int p   = idx >> 8;
            int k   = (idx & 255) + h * 256;
            int na  = base + p;
            int nb  = na + 16;
            float a = 0.f, b = 0.f;
            if (k < KU) {
                if (na < Nn) a = g_U[(size_t)na * KU + k];
                if (nb < Nn) b = g_U[(size_t)nb * KU + k];
            } else {
                int kx = k - KU;
                if (na < Nn) a = x[(size_t)na * DD + kx];
                if (nb < Nn) b = x[(size_t)nb * DD + kx];
            }
            float2 v = make_float2(a, b);
            u2[idx] = *reinterpret_cast<ull*>(&v);
        }
        __syncthreads();

#pragma unroll 2
        for (int kk = 0; kk < 64; kk++) {
            int kg = h * 64 + kk;
            const float4* wrow = reinterpret_cast<const float4*>(g_Wp + kg * 256 + cg * 8);
            float4 wa = __ldg(wrow);
            float4 wb = __ldg(wrow + 1);
            ull wA0 = pk2(wa.x), wA1 = pk2(wa.y), wA2 = pk2(wa.z), wA3 = pk2(wa.w);
            ull wB0 = pk2(wb.x), wB1 = pk2(wb.y), wB2 = pk2(wb.z), wB3 = pk2(wb.w);
#pragma unroll
            for (int q = 0; q < 4; q++) {
                const ulonglong2* up =
                    reinterpret_cast<const ulonglong2*>(&u2[(g * 4 + q) * 256 + 4 * kk]);
                ulonglong2 p0 = up[0];   // i0, i1
                ulonglong2 p1 = up[1];   // i2, i3
                acc[q][0] = f2fma(wA0, p0.x, acc[q][0]);
                acc[q][1] = f2fma(wB0, p0.x, acc[q][1]);
                acc[q][0] = f2fma(wA1, p0.y, acc[q][0]);
                acc[q][1] = f2fma(wB1, p0.y, acc[q][1]);
                acc[q][0] = f2fma(wA2, p1.x, acc[q][0]);
                acc[q][1] = f2fma(wB2, p1.x, acc[q][1]);
                acc[q][0] = f2fma(wA3, p1.y, acc[q][0]);
                acc[q][1] = f2fma(wB3, p1.y, acc[q][1]);
            }
        }
    }

    // epilogue: relu + coalesced STG.64
#pragma unroll
    for (int q = 0; q < 4; q++) {
        float2 a0 = up2(acc[q][0]);
        float2 a1 = up2(acc[q][1]);
        int p  = g * 4 + q;
        int n0 = base + p;
        int n1 = n0 + 16;
        if (n0 < Nn) {
            float2 o = make_float2(fmaxf(a0.x, 0.f), fmaxf(a1.x, 0.f));
            *reinterpret_cast<float2*>(out + (size_t)n0 * DD + 2 * cg) = o;
        }
        if (n1 < Nn) {
            float2 o = make_float2(fmaxf(a0.y, 0.f), fmaxf(a1.y, 0.f));
            *reinterpret_cast<float2*>(out + (size_t)n1 * DD + 2 * cg) = o;
        }
    }
}

// ---------------------------------------------------------------------------
extern "C" void kernel_launch(void* const* d_in, const int* in_sizes, int n_in,
                              void* d_out, int out_size) {
    const float* x      = (const float*)d_in[0];
    const int*   elist  = (const int*)  d_in[1];
    const float* ew     = (const float*)d_in[2];
    const float* ef     = (const float*)d_in[3];
    const float* W_lin  = (const float*)d_in[4];
    const float* b_lin  = (const float*)d_in[5];
    const float* W_self = (const float*)d_in[6];
    const float* b_self = (const float*)d_in[7];
    const float* W_edge = (const float*)d_in[8];
    const float* b_edge = (const float*)d_in[9];
    float*       out    = (float*)d_out;

    int E = in_sizes[2];            // edge_weight element count
    int N = in_sizes[0] / DD;       // x element count / D

    prep_kernel<<<64, 256>>>(W_lin, b_lin, W_self, b_self);

    // counting sort by destination node
    zcnt_kernel<<<(NN + 1023) / 1024, 1024>>>();
    hist_kernel<<<512, 256>>>(elist, E);
    scan_kernel<<<1, 1024>>>(E);
    scatter_kernel<<<512, 256>>>(elist, E);

    // atomic-free edge accumulation (also covers zero-init of g_U)
    edge_sorted_kernel<<<(N + 31) / 32, 512>>>(x, elist, ew, ef, W_edge, b_edge, E, N);

    out_kernel<<<(N + 31) / 32, 128>>>(x, out, N);
}

// round 10
// speedup vs baseline: 1.3461x; 1.3461x over previous
#include <cuda_runtime.h>
#include <cuda_bf16.h>
#include <cstdint>

#define NN    100000
#define RR    7
#define DD    64
#define EDIM  16
#define KU    448              // R*D
#define KTOT  512              // 448 (U) + 64 (x)
#define EMAX  1600000
#define SCAN_BLOCKS ((NN + 1023) / 1024)   // 98

typedef unsigned long long ull;

// Scratch
__device__ float g_U[(size_t)NN * KU];              // 179.2 MB (written once, no atomics)
__device__ float g_Wp[128 * 32 * 8];                // 128 KB interleaved combined weights
__device__ float g_bias[DD];
__device__ int   g_cnt[NN];                         // per-node edge counts
__device__ int   g_start[NN + 1];                   // CSR offsets (preserved)
__device__ int   g_ofs[NN];                         // working cursor for scatter
__device__ int   g_eord[EMAX];                      // edge indices sorted by dest node
__device__ int   g_bsum[SCAN_BLOCKS];               // per-block sums for scan
__device__ int   g_bofs[SCAN_BLOCKS];               // exclusive-scanned block offsets

// ---- f32x2 helpers (sm_103a packed FMA) -----------------------------------
__device__ __forceinline__ ull f2fma(ull a, ull b, ull c) {
    ull d; asm("fma.rn.f32x2 %0, %1, %2, %3;" : "=l"(d) : "l"(a), "l"(b), "l"(c)); return d;
}
__device__ __forceinline__ ull pk2(float w) {
    ull r; asm("mov.b64 %0, {%1, %1};" : "=l"(r) : "f"(w)); return r;
}
__device__ __forceinline__ float2 up2(ull v) {
    float2 r; asm("mov.b64 {%0, %1}, %2;" : "=f"(r.x), "=f"(r.y) : "l"(v)); return r;
}

// ---------------------------------------------------------------------------
// K0: build interleaved combined weight + bias
// ---------------------------------------------------------------------------
__global__ void prep_kernel(const float* __restrict__ W_lin,  const float* __restrict__ b_lin,
                            const float* __restrict__ W_self, const float* __restrict__ b_self) {
    int tid = blockIdx.x * blockDim.x + threadIdx.x;
    const int total = 128 * 32 * 8;
    for (int idx = tid; idx < total; idx += gridDim.x * blockDim.x) {
        int kk  = idx >> 8;
        int rem = idx & 255;
        int cg  = rem >> 3;
        int r8  = rem & 7;
        int s   = r8 >> 2;
        int j   = r8 & 3;
        int col = 2 * cg + s;
        int k   = 4 * kk + j;
        float v = (k < KU) ? W_lin[col * KU + k]
                           : W_self[col * DD + (k - KU)];
        g_Wp[idx] = v;
    }
    if (tid < DD) g_bias[tid] = b_lin[tid] + b_self[tid];
}

// ---------------------------------------------------------------------------
// Sort pipeline: zero -> histogram -> 3-phase parallel scan -> scatter
// ---------------------------------------------------------------------------
__global__ void zcnt_kernel() {
    int i = blockIdx.x * blockDim.x + threadIdx.x;
    if (i < NN) g_cnt[i] = 0;
}

__global__ void hist_kernel(const int* __restrict__ elist, int E) {
    int stride = gridDim.x * blockDim.x;
    for (int e = blockIdx.x * blockDim.x + threadIdx.x; e < E; e += stride) {
        int no = elist[3 * e + 1];
        atomicAdd(&g_cnt[no], 1);
    }
}

// Phase 1: per-block inclusive scan of 1024 counts; write exclusive partials.
__global__ void pscan_kernel() {     // <<<SCAN_BLOCKS, 1024>>>
    __shared__ int sh[1024];
    int t = threadIdx.x;
    int i = blockIdx.x * 1024 + t;
    int c = (i < NN) ? g_cnt[i] : 0;
    sh[t] = c;
    __syncthreads();
#pragma unroll
    for (int off = 1; off < 1024; off <<= 1) {
        int v = (t >= off) ? sh[t - off] : 0;
        __syncthreads();
        sh[t] += v;
        __syncthreads();
    }
    if (i < NN) g_start[i] = sh[t] - c;          // exclusive within block
    if (t == 1023) g_bsum[blockIdx.x] = sh[1023];
}

// Phase 2: exclusive scan of the 98 block sums (one tiny block).
__global__ void bscan_kernel() {     // <<<1, 128>>>
    __shared__ int sh[128];
    int t = threadIdx.x;
    int v = (t < SCAN_BLOCKS) ? g_bsum[t] : 0;
    sh[t] = v;
    __syncthreads();
#pragma unroll
    for (int off = 1; off < 128; off <<= 1) {
        int u = (t >= off) ? sh[t - off] : 0;
        __syncthreads();
        sh[t] += u;
        __syncthreads();
    }
    if (t < SCAN_BLOCKS) g_bofs[t] = sh[t] - v;  // exclusive
    if (t == 127) g_start[NN] = sh[127];         // == E
}

// Phase 3: add block offsets; init scatter cursors.
__global__ void addofs_kernel() {    // <<<SCAN_BLOCKS, 1024>>>
    int i = blockIdx.x * 1024 + threadIdx.x;
    if (i < NN) {
        int v = g_start[i] + g_bofs[blockIdx.x];
        g_start[i] = v;
        g_ofs[i]   = v;
    }
}

__global__ void scatter_kernel(const int* __restrict__ elist, int E) {
    int stride = gridDim.x * blockDim.x;
    for (int e = blockIdx.x * blockDim.x + threadIdx.x; e < E; e += stride) {
        int no  = elist[3 * e + 1];
        int pos = atomicAdd(&g_ofs[no], 1);
        g_eord[pos] = e;
    }
}

// ---------------------------------------------------------------------------
// K2: sorted edge accumulation, NO atomics, software-pipelined edge loads.
//     Block = 32 nodes, 512 threads. 16-lane group gi owns node base+gi and
//     processes all its edges sequentially into its exclusive smem U-row.
// ---------------------------------------------------------------------------
__global__ __launch_bounds__(512) void edge_sorted_kernel(
        const float* __restrict__ x,
        const int*   __restrict__ elist,
        const float* __restrict__ ew,
        const float* __restrict__ ef,
        const float* __restrict__ W_edge,
        const float* __restrict__ b_edge,
        int E, int Nn) {
    __shared__ float4 We_sh[EDIM * 16];   // We_sh[d*16+t] = W_edge rows 4t..4t+3, dim d
    __shared__ float4 be_sh[16];
    __shared__ float  U_sh[32 * KU];      // 56 KB, one 448-row per node

    int tid = threadIdx.x;
    if (tid < 256) {
        int d = tid / 16, t = tid % 16;
        float4 v;
        v.x = W_edge[(4 * t + 0) * EDIM + d];
        v.y = W_edge[(4 * t + 1) * EDIM + d];
        v.z = W_edge[(4 * t + 2) * EDIM + d];
        v.w = W_edge[(4 * t + 3) * EDIM + d];
        We_sh[tid] = v;
        if (tid < 16) be_sh[tid] = reinterpret_cast<const float4*>(b_edge)[tid];
    }
    float4* U4 = reinterpret_cast<float4*>(U_sh);
#pragma unroll
    for (int it = 0; it < 7; it++)
        U4[it * 512 + tid] = make_float4(0.f, 0.f, 0.f, 0.f);
    __syncthreads();

    int gi = tid >> 4;          // group 0..31 -> node
    int t  = tid & 15;          // lane within group -> dims 4t..4t+3
    int n  = blockIdx.x * 32 + gi;

    if (n < Nn) {
        int s0 = g_start[n];
        int s1 = g_start[n + 1];
        float* Urow = U_sh + gi * KU;

        if (s0 < s1) {
            // ---- prologue: load edge s0's data ----
            int e = g_eord[s0];
            int   ni  = elist[3 * e + 0];
            int   rel = elist[3 * e + 2];
            float w   = ew[e];
            const float4* ev = reinterpret_cast<const float4*>(ef + (size_t)e * EDIM);
            float4 f0 = ev[0], f1 = ev[1], f2 = ev[2], f3 = ev[3];
            float4 xg = reinterpret_cast<const float4*>(x + (size_t)ni * DD)[t];

            for (int s = s0; s < s1; s++) {
                // ---- prefetch next edge's data (overlaps current compute) ----
                int e2 = (s + 1 < s1) ? g_eord[s + 1] : e;
                int   ni2  = elist[3 * e2 + 0];
                int   rel2 = elist[3 * e2 + 2];
                float w2   = ew[e2];
                const float4* ev2 = reinterpret_cast<const float4*>(ef + (size_t)e2 * EDIM);
                float4 n0 = ev2[0], n1 = ev2[1], n2 = ev2[2], n3 = ev2[3];
                float4 xg2 = reinterpret_cast<const float4*>(x + (size_t)ni2 * DD)[t];

                // ---- compute current edge ----
                float4 acc = be_sh[t];
                {
                    float vals0[4] = {f0.x, f0.y, f0.z, f0.w};
                    float vals1[4] = {f1.x, f1.y, f1.z, f1.w};
                    float vals2[4] = {f2.x, f2.y, f2.z, f2.w};
                    float vals3[4] = {f3.x, f3.y, f3.z, f3.w};
#pragma unroll
                    for (int q = 0; q < 4; q++) {
                        float4 wv = We_sh[(0 + q) * 16 + t];
                        acc.x += wv.x * vals0[q]; acc.y += wv.y * vals0[q];
                        acc.z += wv.z * vals0[q]; acc.w += wv.w * vals0[q];
                    }
#pragma unroll
                    for (int q = 0; q < 4; q++) {
                        float4 wv = We_sh[(4 + q) * 16 + t];
                        acc.x += wv.x * vals1[q]; acc.y += wv.y * vals1[q];
                        acc.z += wv.z * vals1[q]; acc.w += wv.w * vals1[q];
                    }
#pragma unroll
                    for (int q = 0; q < 4; q++) {
                        float4 wv = We_sh[(8 + q) * 16 + t];
                        acc.x += wv.x * vals2[q]; acc.y += wv.y * vals2[q];
                        acc.z += wv.z * vals2[q]; acc.w += wv.w * vals2[q];
                    }
#pragma unroll
                    for (int q = 0; q < 4; q++) {
                        float4 wv = We_sh[(12 + q) * 16 + t];
                        acc.x += wv.x * vals3[q]; acc.y += wv.y * vals3[q];
                        acc.z += wv.z * vals3[q]; acc.w += wv.w * vals3[q];
                    }
                }
                float4* dst = reinterpret_cast<float4*>(Urow + rel * DD + 4 * t);
                float4 cur = *dst;
                cur.x += w * (xg.x + acc.x);
                cur.y += w * (xg.y + acc.y);
                cur.z += w * (xg.z + acc.z);
                cur.w += w * (xg.w + acc.w);
                *dst = cur;

                // ---- rotate ----
                e = e2; ni = ni2; rel = rel2; w = w2;
                f0 = n0; f1 = n1; f2 = n2; f3 = n3; xg = xg2;
            }
        }
    }
    __syncthreads();

    // dump all 32 rows to g_U, coalesced (rows of empty nodes stay zero)
    int base = blockIdx.x * 32;
#pragma unroll
    for (int it = 0; it < 7; it++) {
        int idx = it * 512 + tid;
        int nl  = idx / 112;          // 448/4 float4s per row
        int k4  = idx % 112;
        int n2  = base + nl;
        if (n2 < Nn)
            reinterpret_cast<float4*>(g_U + (size_t)n2 * KU)[k4] = U4[idx];
    }
}

// ---------------------------------------------------------------------------
// K3: register-blocked GEMM with packed f32x2 FMA, K-split staging (2 x 32KB).
//     out = relu([U‖x](N x 512) @ Wc(512 x 64) + bias)
// ---------------------------------------------------------------------------
__global__ __launch_bounds__(128) void out_kernel(const float* __restrict__ x,
                                                  float* __restrict__ out, int Nn) {
    __shared__ __align__(16) ull u2[16 * 256];   // 16 pairs x 256 k-slice
    int tid  = threadIdx.x;
    int base = blockIdx.x * 32;

    int cg = tid & 31;
    int g  = tid >> 5;

    float bc0 = g_bias[2 * cg];
    float bc1 = g_bias[2 * cg + 1];
    ull acc[4][2];
#pragma unroll
    for (int q = 0; q < 4; q++) { acc[q][0] = pk2(bc0); acc[q][1] = pk2(bc1); }

#pragma unroll
    for (int h = 0; h < 2; h++) {
        if (h) __syncthreads();

        // stage k in [h*256, h*256+256), pre-packed float2, coalesced
#pragma unroll
        for (int it = 0; it < 32; it++) {
            int idx = it * 128 + tid;
            int p   = idx >> 8;
            int k   = (idx & 255) + h * 256;
            int na  = base + p;
            int nb  = na + 16;
            float a = 0.f, b = 0.f;
            if (k < KU) {
                if (na < Nn) a = g_U[(size_t)na * KU + k];
                if (nb < Nn) b = g_U[(size_t)nb * KU + k];
            } else {
                int kx = k - KU;
                if (na < Nn) a = x[(size_t)na * DD + kx];
                if (nb < Nn) b = x[(size_t)nb * DD + kx];
            }
            float2 v = make_float2(a, b);
            u2[idx] = *reinterpret_cast<ull*>(&v);
        }
        __syncthreads();

#pragma unroll 2
        for (int kk = 0; kk < 64; kk++) {
            int kg = h * 64 + kk;
            const float4* wrow = reinterpret_cast<const float4*>(g_Wp + kg * 256 + cg * 8);
            float4 wa = __ldg(wrow);
            float4 wb = __ldg(wrow + 1);
            ull wA0 = pk2(wa.x), wA1 = pk2(wa.y), wA2 = pk2(wa.z), wA3 = pk2(wa.w);
            ull wB0 = pk2(wb.x), wB1 = pk2(wb.y), wB2 = pk2(wb.z), wB3 = pk2(wb.w);
#pragma unroll
            for (int q = 0; q < 4; q++) {
                const ulonglong2* up =
                    reinterpret_cast<const ulonglong2*>(&u2[(g * 4 + q) * 256 + 4 * kk]);
                ulonglong2 p0 = up[0];   // i0, i1
                ulonglong2 p1 = up[1];   // i2, i3
                acc[q][0] = f2fma(wA0, p0.x, acc[q][0]);
                acc[q][1] = f2fma(wB0, p0.x, acc[q][1]);
                acc[q][0] = f2fma(wA1, p0.y, acc[q][0]);
                acc[q][1] = f2fma(wB1, p0.y, acc[q][1]);
                acc[q][0] = f2fma(wA2, p1.x, acc[q][0]);
                acc[q][1] = f2fma(wB2, p1.x, acc[q][1]);
                acc[q][0] = f2fma(wA3, p1.y, acc[q][0]);
                acc[q][1] = f2fma(wB3, p1.y, acc[q][1]);
            }
        }
    }

    // epilogue: relu + coalesced STG.64
#pragma unroll
    for (int q = 0; q < 4; q++) {
        float2 a0 = up2(acc[q][0]);
        float2 a1 = up2(acc[q][1]);
        int p  = g * 4 + q;
        int n0 = base + p;
        int n1 = n0 + 16;
        if (n0 < Nn) {
            float2 o = make_float2(fmaxf(a0.x, 0.f), fmaxf(a1.x, 0.f));
            *reinterpret_cast<float2*>(out + (size_t)n0 * DD + 2 * cg) = o;
        }
        if (n1 < Nn) {
            float2 o = make_float2(fmaxf(a0.y, 0.f), fmaxf(a1.y, 0.f));
            *reinterpret_cast<float2*>(out + (size_t)n1 * DD + 2 * cg) = o;
        }
    }
}

// ---------------------------------------------------------------------------
extern "C" void kernel_launch(void* const* d_in, const int* in_sizes, int n_in,
                              void* d_out, int out_size) {
    const float* x      = (const float*)d_in[0];
    const int*   elist  = (const int*)  d_in[1];
    const float* ew     = (const float*)d_in[2];
    const float* ef     = (const float*)d_in[3];
    const float* W_lin  = (const float*)d_in[4];
    const float* b_lin  = (const float*)d_in[5];
    const float* W_self = (const float*)d_in[6];
    const float* b_self = (const float*)d_in[7];
    const float* W_edge = (const float*)d_in[8];
    const float* b_edge = (const float*)d_in[9];
    float*       out    = (float*)d_out;

    int E = in_sizes[2];            // edge_weight element count
    int N = in_sizes[0] / DD;       // x element count / D

    prep_kernel<<<64, 256>>>(W_lin, b_lin, W_self, b_self);

    // counting sort by destination node (parallel scan)
    zcnt_kernel<<<SCAN_BLOCKS, 1024>>>();
    hist_kernel<<<512, 256>>>(elist, E);
    pscan_kernel<<<SCAN_BLOCKS, 1024>>>();
    bscan_kernel<<<1, 128>>>();
    addofs_kernel<<<SCAN_BLOCKS, 1024>>>();
    scatter_kernel<<<512, 256>>>(elist, E);

    // atomic-free edge accumulation (also covers zero-init of g_U)
    edge_sorted_kernel<<<(N + 31) / 32, 512>>>(x, elist, ew, ef, W_edge, b_edge, E, N);

    out_kernel<<<(N + 31) / 32, 128>>>(x, out, N);
}